// round 14
// baseline (speedup 1.0000x reference)
#include <cuda_runtime.h>

// Problem constants
#define BB 4
#define SQ 4096
#define EE 256
#define M_TOT (BB*SQ)        // 16384 rows
#define BQ 64
#define BK 64
#define QT_STRIDE 68          // 64 + 4 pad: 272B rows -> 16B aligned, tolerable STS conflicts

// ---------------- scratch (static device globals; no allocation) ----------------
__device__ __align__(16) float g_q[BB*SQ*EE];
__device__ __align__(16) float g_k[BB*SQ*EE];
__device__ __align__(16) float g_v[BB*SQ*EE];
__device__ __align__(16) float g_attn[BB*SQ*EE];
__device__ __align__(16) float g_o1[BB*SQ*EE];

typedef unsigned long long ull;

// ---------------- packed f32x2 helpers (FFMA2 path: 2x FFMA throughput) ----------------
__device__ __forceinline__ ull pack2(float lo, float hi) {
    ull r; asm("mov.b64 %0, {%1,%2};" : "=l"(r) : "f"(lo), "f"(hi)); return r;
}
__device__ __forceinline__ ull dup2(float x) { return pack2(x, x); }
__device__ __forceinline__ float2 unpack2(ull v) {
    float2 f; asm("mov.b64 {%0,%1}, %2;" : "=f"(f.x), "=f"(f.y) : "l"(v)); return f;
}
__device__ __forceinline__ void ffma2(ull& d, ull a, ull b) {
    asm("fma.rn.f32x2 %0, %1, %2, %0;" : "+l"(d) : "l"(a), "l"(b));
}
__device__ __forceinline__ void fmul2(ull& d, ull a) {
    asm("mul.rn.f32x2 %0, %0, %1;" : "+l"(d) : "l"(a));
}

// ---------------- QKV projection: out[m,o] = sum_e X[m,e] * W[o,e] + bias[o] ----------------
// grid = (M/64, E/64, 3), block = 256. z selects Q/K/V weight.
__global__ __launch_bounds__(256, 1) void qkv_gemm_kernel(
    const float* __restrict__ X,
    const float* __restrict__ Wq, const float* __restrict__ bq,
    const float* __restrict__ Wk, const float* __restrict__ bk,
    const float* __restrict__ Wv, const float* __restrict__ bv,
    float* __restrict__ Qo, float* __restrict__ Ko, float* __restrict__ Vo)
{
    __shared__ __align__(16) float Xt[64][QT_STRIDE];   // [k][m]
    __shared__ __align__(16) float Wt[64][QT_STRIDE];   // [k][o]

    const float* W; const float* bias; float* out;
    if (blockIdx.z == 0)      { W = Wq; bias = bq; out = Qo; }
    else if (blockIdx.z == 1) { W = Wk; bias = bk; out = Ko; }
    else                      { W = Wv; bias = bv; out = Vo; }

    const int m0 = blockIdx.x * 64;
    const int o0 = blockIdx.y * 64;
    const int tid  = threadIdx.x;
    const int lane = tid & 31, warp = tid >> 5;
    const int c0 = lane * 2, w8 = warp * 8;
    const int e_l = tid & 63;     // k within tile
    const int mq  = tid >> 6;     // 0..3

    ull acc[4][2] = {};

    for (int kt = 0; kt < EE / 64; kt++) {
        __syncthreads();
        // stage transposed tiles: Xt[e][m], Wt[e][o]
        #pragma unroll
        for (int i = 0; i < 16; i++) {
            int m = mq * 16 + i;
            Xt[e_l][m] = X[(size_t)(m0 + m) * EE + kt * 64 + e_l];
            Wt[e_l][m] = W[(size_t)(o0 + m) * EE + kt * 64 + e_l];
        }
        __syncthreads();
        #pragma unroll 8
        for (int k = 0; k < 64; k++) {
            const float* xr = &Xt[k][w8];
            ulonglong2 a01 = *(const ulonglong2*)xr;        // rows (w8,w8+1),(w8+2,w8+3)
            ulonglong2 a23 = *(const ulonglong2*)(xr + 4);  // rows (w8+4..w8+7)
            float2 bv2 = *(const float2*)&Wt[k][c0];
            ull b0 = dup2(bv2.x), b1 = dup2(bv2.y);
            ffma2(acc[0][0], a01.x, b0); ffma2(acc[0][1], a01.x, b1);
            ffma2(acc[1][0], a01.y, b0); ffma2(acc[1][1], a01.y, b1);
            ffma2(acc[2][0], a23.x, b0); ffma2(acc[2][1], a23.x, b1);
            ffma2(acc[3][0], a23.y, b0); ffma2(acc[3][1], a23.y, b1);
        }
    }
    const float b0f = bias[o0 + c0];
    const float b1f = bias[o0 + c0 + 1];
    #pragma unroll
    for (int p = 0; p < 4; p++) {
        float2 f0 = unpack2(acc[p][0]);   // col c0, rows (even, odd)
        float2 f1 = unpack2(acc[p][1]);   // col c0+1
        size_t r0 = (size_t)(m0 + w8 + 2 * p) * EE + o0 + c0;
        *(float2*)&out[r0]      = make_float2(f0.x + b0f, f1.x + b1f);
        *(float2*)&out[r0 + EE] = make_float2(f0.y + b0f, f1.y + b1f);
    }
}

// ---------------- Flash attention, fp32, online softmax ----------------
// grid = (S/BQ, B), block = 256 (8 warps). Warp w owns q-rows w*8..w*8+7 of the tile
// in BOTH phases, so softmax stats stay in registers and P never crosses warps.
__global__ __launch_bounds__(256, 1) void flash_kernel(
    const float* __restrict__ Q, const float* __restrict__ K, const float* __restrict__ V,
    float* __restrict__ O)
{
    extern __shared__ __align__(16) float sm[];
    float* Qt = sm;                          // [E][QT_STRIDE]  (e-major, scaled)
    float* Kt = Qt + EE * QT_STRIDE;         // [E][QT_STRIDE]
    float* Vs = Kt + EE * QT_STRIDE;         // [BK][E]
    float* Ps = Vs + BK * EE;                // [BQ][BK]

    const int b  = blockIdx.y;
    const int q0 = blockIdx.x * BQ;
    const size_t base = (size_t)b * SQ * EE;
    const float* Qb = Q + base + (size_t)q0 * EE;
    const float* Kb = K + base;
    const float* Vb = V + base;

    const int tid  = threadIdx.x;
    const int lane = tid & 31, warp = tid >> 5;
    const int c0 = lane * 2, w8 = warp * 8;
    const int e8 = lane * 8;

    // stage Q transposed, pre-scaled by 1/sqrt(S) = 1/64
    {
        const float scale = 1.0f / 64.0f;
        #pragma unroll 4
        for (int i = 0; i < BQ; i++)
            Qt[(size_t)tid * QT_STRIDE + i] = Qb[(size_t)i * EE + tid] * scale;
    }

    float m_r[8], l_r[8];
    #pragma unroll
    for (int r = 0; r < 8; r++) { m_r[r] = -1e30f; l_r[r] = 0.0f; }
    ull o2[8][4] = {};   // O accumulators: 8 q-rows x 4 e-pairs (e8..e8+7)

    for (int t = 0; t < SQ / BK; t++) {
        __syncthreads();   // previous tile's Vs reads done; Qt staged (t==0)
        // stage K transposed + V row-major
        {
            const float* Kp = Kb + (size_t)t * BK * EE;
            #pragma unroll 4
            for (int i = 0; i < BK; i++)
                Kt[(size_t)tid * QT_STRIDE + i] = Kp[(size_t)i * EE + tid];
            const float4* V4 = (const float4*)(Vb + (size_t)t * BK * EE);
            float4* Vs4 = (float4*)Vs;
            #pragma unroll
            for (int i = 0; i < 16; i++)
                Vs4[tid + i * 256] = V4[tid + i * 256];
        }
        __syncthreads();

        // --- S = Q K^T (tile 64x64); thread: rows w8..w8+7 (pairs), cols c0,c0+1 ---
        ull acc[4][2] = {};
        #pragma unroll 4
        for (int k = 0; k < EE; k++) {
            const float* qr = &Qt[k * QT_STRIDE + w8];
            ulonglong2 a01 = *(const ulonglong2*)qr;
            ulonglong2 a23 = *(const ulonglong2*)(qr + 4);
            float2 bv2 = *(const float2*)&Kt[k * QT_STRIDE + c0];
            ull b0 = dup2(bv2.x), b1 = dup2(bv2.y);
            ffma2(acc[0][0], a01.x, b0); ffma2(acc[0][1], a01.x, b1);
            ffma2(acc[1][0], a01.y, b0); ffma2(acc[1][1], a01.y, b1);
            ffma2(acc[2][0], a23.x, b0); ffma2(acc[2][1], a23.x, b1);
            ffma2(acc[3][0], a23.y, b0); ffma2(acc[3][1], a23.y, b1);
        }
        float sv[8][2];
        #pragma unroll
        for (int p = 0; p < 4; p++) {
            float2 f0 = unpack2(acc[p][0]);
            float2 f1 = unpack2(acc[p][1]);
            sv[2*p][0]   = f0.x;  sv[2*p][1]   = f1.x;
            sv[2*p+1][0] = f0.y;  sv[2*p+1][1] = f1.y;
        }

        // --- online softmax per row (row data spread across the 32 lanes of this warp) ---
        float alpha[8];
        #pragma unroll
        for (int r = 0; r < 8; r++) {
            float mx = fmaxf(sv[r][0], sv[r][1]);
            #pragma unroll
            for (int sh = 16; sh; sh >>= 1)
                mx = fmaxf(mx, __shfl_xor_sync(0xffffffffu, mx, sh));
            float mnew = fmaxf(m_r[r], mx);
            float a  = __expf(m_r[r] - mnew);
            float p0 = __expf(sv[r][0] - mnew);
            float p1 = __expf(sv[r][1] - mnew);
            float s = p0 + p1;
            #pragma unroll
            for (int sh = 16; sh; sh >>= 1)
                s += __shfl_xor_sync(0xffffffffu, s, sh);
            l_r[r] = l_r[r] * a + s;
            m_r[r] = mnew;
            alpha[r] = a;
            *(float2*)&Ps[(w8 + r) * BK + c0] = make_float2(p0, p1);
        }
        __syncwarp();   // Ps rows w8..w8+7 written only by this warp

        // --- O = O*alpha + P V ; thread: rows w8..w8+7, e cols e8..e8+7 ---
        #pragma unroll
        for (int r = 0; r < 8; r++) {
            ull ad = dup2(alpha[r]);
            fmul2(o2[r][0], ad); fmul2(o2[r][1], ad);
            fmul2(o2[r][2], ad); fmul2(o2[r][3], ad);
        }
        #pragma unroll 2
        for (int kv = 0; kv < BK; kv++) {
            const float* vr = &Vs[kv * EE + e8];
            ulonglong2 v01 = *(const ulonglong2*)vr;
            ulonglong2 v23 = *(const ulonglong2*)(vr + 4);
            #pragma unroll
            for (int r = 0; r < 8; r++) {
                ull pd = dup2(Ps[(w8 + r) * BK + kv]);
                ffma2(o2[r][0], pd, v01.x); ffma2(o2[r][1], pd, v01.y);
                ffma2(o2[r][2], pd, v23.x); ffma2(o2[r][3], pd, v23.y);
            }
        }
    }

    // epilogue: normalize by l, store
    #pragma unroll
    for (int r = 0; r < 8; r++) {
        ull iv = dup2(1.0f / l_r[r]);
        fmul2(o2[r][0], iv); fmul2(o2[r][1], iv);
        fmul2(o2[r][2], iv); fmul2(o2[r][3], iv);
        float* orow = O + base + (size_t)(q0 + w8 + r) * EE + e8;
        float2 f0 = unpack2(o2[r][0]), f1 = unpack2(o2[r][1]);
        float2 f2 = unpack2(o2[r][2]), f3 = unpack2(o2[r][3]);
        *(float4*)orow       = make_float4(f0.x, f0.y, f1.x, f1.y);
        *(float4*)(orow + 4) = make_float4(f2.x, f2.y, f3.x, f3.y);
    }
}

// ---------------- residual add + LayerNorm (biased var, eps=1e-5) ----------------
// grid = M_TOT, block = 256 (one element per thread).
__global__ __launch_bounds__(256, 1) void add_ln_kernel(
    const float* __restrict__ A, const float* __restrict__ R,
    const float* __restrict__ g, const float* __restrict__ beta,
    float* __restrict__ out)
{
    __shared__ float red0[8];
    __shared__ float red1[8];
    const int row = blockIdx.x;
    const int e   = threadIdx.x;
    const size_t idx = (size_t)row * EE + e;
    float v  = A[idx] + R[idx];
    float s  = v;
    float s2 = v * v;
    #pragma unroll
    for (int sh = 16; sh; sh >>= 1) {
        s  += __shfl_xor_sync(0xffffffffu, s,  sh);
        s2 += __shfl_xor_sync(0xffffffffu, s2, sh);
    }
    const int lane = e & 31, warp = e >> 5;
    if (lane == 0) { red0[warp] = s; red1[warp] = s2; }
    __syncthreads();
    if (warp == 0) {
        float a  = red0[lane & 7];
        float b2 = red1[lane & 7];
        #pragma unroll
        for (int sh = 4; sh; sh >>= 1) {
            a  += __shfl_xor_sync(0xffffffffu, a,  sh);
            b2 += __shfl_xor_sync(0xffffffffu, b2, sh);
        }
        if (lane == 0) { red0[0] = a; red1[0] = b2; }
    }
    __syncthreads();
    const float mu  = red0[0] * (1.0f / EE);
    const float var = red1[0] * (1.0f / EE) - mu * mu;
    const float rs  = rsqrtf(var + 1e-5f);
    out[idx] = (v - mu) * rs * g[e] + beta[e];
}

// ---------------- host launch ----------------
extern "C" void kernel_launch(void* const* d_in, const int* in_sizes, int n_in,
                              void* d_out, int out_size)
{
    (void)in_sizes; (void)n_in; (void)out_size;
    const float* x   = (const float*)d_in[0];
    const float* Wq1 = (const float*)d_in[1];
    const float* bq1 = (const float*)d_in[2];
    const float* Wk1 = (const float*)d_in[3];
    const float* bk1 = (const float*)d_in[4];
    const float* Wv1 = (const float*)d_in[5];
    const float* bv1 = (const float*)d_in[6];
    const float* Wq2 = (const float*)d_in[7];
    const float* bq2 = (const float*)d_in[8];
    const float* Wk2 = (const float*)d_in[9];
    const float* bk2 = (const float*)d_in[10];
    const float* Wv2 = (const float*)d_in[11];
    const float* bv2 = (const float*)d_in[12];
    const float* g1  = (const float*)d_in[13];
    const float* be1 = (const float*)d_in[14];
    const float* g2  = (const float*)d_in[15];
    const float* be2 = (const float*)d_in[16];
    float* out = (float*)d_out;

    float *qb, *kb, *vb, *ab, *ob;
    cudaGetSymbolAddress((void**)&qb, g_q);
    cudaGetSymbolAddress((void**)&kb, g_k);
    cudaGetSymbolAddress((void**)&vb, g_v);
    cudaGetSymbolAddress((void**)&ab, g_attn);
    cudaGetSymbolAddress((void**)&ob, g_o1);

    const int smem_flash = (EE * QT_STRIDE * 2 + BK * EE + BQ * BK) * (int)sizeof(float); // 221184 B
    cudaFuncSetAttribute(flash_kernel, cudaFuncAttributeMaxDynamicSharedMemorySize, smem_flash);

    dim3 gq(M_TOT / 64, EE / 64, 3);
    dim3 gf(SQ / BQ, BB);

    // layer 1
    qkv_gemm_kernel<<<gq, 256>>>(x, Wq1, bq1, Wk1, bk1, Wv1, bv1, qb, kb, vb);
    flash_kernel<<<gf, 256, smem_flash>>>(qb, kb, vb, ab);
    add_ln_kernel<<<M_TOT, 256>>>(ab, x, g1, be1, ob);
    // layer 2
    qkv_gemm_kernel<<<gq, 256>>>(ob, Wq2, bq2, Wk2, bk2, Wv2, bv2, qb, kb, vb);
    flash_kernel<<<gf, 256, smem_flash>>>(qb, kb, vb, ab);
    add_ln_kernel<<<M_TOT, 256>>>(ab, ob, g2, be2, out);
}

// round 15
// speedup vs baseline: 1.4316x; 1.4316x over previous
#include <cuda_runtime.h>
#include <stdint.h>

// Problem constants
#define BB 4
#define SQ 4096
#define EE 256
#define M_TOT (BB*SQ)        // 16384 rows
#define BQ 64
#define BK 64

// ---------------- scratch (static device globals; no allocation) ----------------
__device__ __align__(16) float g_qt[BB*SQ*EE];     // Q transposed [B][E][S], pre-scaled
__device__ __align__(16) float g_kt[BB*SQ*EE];     // K transposed [B][E][S]
__device__ __align__(16) float g_v [BB*SQ*EE];     // V row-major  [B][S][E]
__device__ __align__(16) float g_attn[BB*SQ*EE];   // attention out, row-major
__device__ __align__(16) float g_o1[BB*SQ*EE];     // layer-1 output, row-major
__device__ __align__(16) float g_xt[BB*SQ*EE];     // qkv input, transposed [B][E][S]
__device__ __align__(16) float g_wt[6*EE*EE];      // 6 transposed weights [E_in][E_out]

typedef unsigned long long ull;

// ---------------- packed f32x2 helpers (FFMA2: 2x fp32 FMA throughput) ----------------
__device__ __forceinline__ ull pack2(float lo, float hi) {
    ull r; asm("mov.b64 %0, {%1,%2};" : "=l"(r) : "f"(lo), "f"(hi)); return r;
}
__device__ __forceinline__ ull dup2(float x) { return pack2(x, x); }
__device__ __forceinline__ float2 unpack2(ull v) {
    float2 f; asm("mov.b64 {%0,%1}, %2;" : "=f"(f.x), "=f"(f.y) : "l"(v)); return f;
}
__device__ __forceinline__ void ffma2(ull& d, ull a, ull b) {
    asm("fma.rn.f32x2 %0, %1, %2, %0;" : "+l"(d) : "l"(a), "l"(b));
}
__device__ __forceinline__ void fmul2(ull& d, ull a) {
    asm("mul.rn.f32x2 %0, %0, %1;" : "+l"(d) : "l"(a));
}

// ---------------- cp.async helpers ----------------
__device__ __forceinline__ uint32_t smem_u32(const void* p) {
    return (uint32_t)__cvta_generic_to_shared(p);
}
__device__ __forceinline__ void cp16(uint32_t dst, const void* src) {
    asm volatile("cp.async.cg.shared.global [%0], [%1], 16;\n" :: "r"(dst), "l"(src));
}
#define CP_COMMIT() asm volatile("cp.async.commit_group;\n" ::: "memory")
#define CP_WAIT0()  asm volatile("cp.async.wait_group 0;\n" ::: "memory")
#define CP_WAIT1()  asm volatile("cp.async.wait_group 1;\n" ::: "memory")

// ---------------- generic slab transpose: in [z][R][C] -> out [z][C][R] ----------------
__global__ void transpose_kernel(const float* __restrict__ in, float* __restrict__ out,
                                 int R, int C)
{
    __shared__ float t[32][33];
    const float* inp = in  + (size_t)blockIdx.z * R * C;
    float*       outp = out + (size_t)blockIdx.z * R * C;
    const int c0 = blockIdx.x * 32, r0 = blockIdx.y * 32;
    const int x = threadIdx.x, y = threadIdx.y;        // block (32, 8)
    #pragma unroll
    for (int j = 0; j < 32; j += 8)
        t[y + j][x] = inp[(size_t)(r0 + y + j) * C + c0 + x];
    __syncthreads();
    #pragma unroll
    for (int j = 0; j < 32; j += 8)
        outp[(size_t)(c0 + y + j) * R + r0 + x] = t[x][y + j];
}

// ---------------- QKV projection ----------------
// Inputs pre-transposed: Xt [B][E][S], Wt [E_in][E_out] per slab.
// Outputs: Q transposed+scaled, K transposed, V row-major.
// grid = (M_TOT/64, EE/64, 3), block = 256. All staging via cp.async (double-buffered).
__global__ __launch_bounds__(256, 1) void qkv_kernel(
    const float* __restrict__ Xt, const float* __restrict__ Wt,
    const float* __restrict__ bq, const float* __restrict__ bk, const float* __restrict__ bv,
    float* __restrict__ Qt, float* __restrict__ Kt, float* __restrict__ V)
{
    extern __shared__ __align__(16) float sm[];
    float* Xs = sm;             // [2][64][64]
    float* Ws = sm + 2 * 4096;  // [2][64][64]

    const int z = blockIdx.z;
    const float* W    = Wt + (size_t)z * EE * EE;
    const float* bias = (z == 0) ? bq : (z == 1) ? bk : bv;

    const int m0 = blockIdx.x * 64;
    const int b  = m0 / SQ, s0 = m0 % SQ;
    const int o0 = blockIdx.y * 64;
    const int tid = threadIdx.x, lane = tid & 31, warp = tid >> 5;
    const int c0 = lane * 2, w8 = warp * 8;
    const int rr = tid >> 4, cc = (tid & 15) * 4;   // staging: row rr(+16j), 16B chunk cc

    const float* xbase = Xt + ((size_t)(b * EE + rr) * SQ + s0) + cc;
    const float* wbase = W  + (size_t)rr * EE + o0 + cc;

    // stage k-tile kt into buffer buf
    auto stage = [&](int kt, int buf) {
        uint32_t xd = smem_u32(Xs + buf * 4096 + rr * 64 + cc);
        uint32_t wd = smem_u32(Ws + buf * 4096 + rr * 64 + cc);
        const float* xs = xbase + (size_t)(kt * 64) * SQ;
        const float* ws = wbase + (size_t)(kt * 64) * EE;
        #pragma unroll
        for (int j = 0; j < 4; j++) {
            cp16(xd + j * (16 * 64 * 4), xs + (size_t)j * 16 * SQ);
            cp16(wd + j * (16 * 64 * 4), ws + (size_t)j * 16 * EE);
        }
        CP_COMMIT();
    };

    stage(0, 0);
    ull acc[4][2] = {};

    for (int kt = 0; kt < 4; kt++) {
        __syncthreads();                  // previous compute's smem reads done
        if (kt < 3) { stage(kt + 1, (kt + 1) & 1); CP_WAIT1(); }
        else        { CP_WAIT0(); }
        __syncthreads();

        const float* Xb = Xs + (kt & 1) * 4096;
        const float* Wb = Ws + (kt & 1) * 4096;
        #pragma unroll 8
        for (int k = 0; k < 64; k++) {
            const float* xr = Xb + k * 64 + w8;          // broadcast within warp
            ulonglong2 a01 = *(const ulonglong2*)xr;
            ulonglong2 a23 = *(const ulonglong2*)(xr + 4);
            float2 bv2 = *(const float2*)(Wb + k * 64 + c0);
            ull b0 = dup2(bv2.x), b1 = dup2(bv2.y);
            ffma2(acc[0][0], a01.x, b0); ffma2(acc[0][1], a01.x, b1);
            ffma2(acc[1][0], a01.y, b0); ffma2(acc[1][1], a01.y, b1);
            ffma2(acc[2][0], a23.x, b0); ffma2(acc[2][1], a23.x, b1);
            ffma2(acc[3][0], a23.y, b0); ffma2(acc[3][1], a23.y, b1);
        }
    }

    const float bias0 = bias[o0 + c0];
    const float bias1 = bias[o0 + c0 + 1];

    if (z == 2) {
        // V: row-major [m][o]
        #pragma unroll
        for (int p = 0; p < 4; p++) {
            float2 f0 = unpack2(acc[p][0]);
            float2 f1 = unpack2(acc[p][1]);
            size_t r0i = (size_t)(m0 + w8 + 2 * p) * EE + o0 + c0;
            *(float2*)&V[r0i]      = make_float2(f0.x + bias0, f1.x + bias1);
            *(float2*)&V[r0i + EE] = make_float2(f0.y + bias0, f1.y + bias1);
        }
    } else {
        // Q/K: transposed [B][E][S]; Q pre-scaled by 1/sqrt(S)=1/64
        const float scale = (z == 0) ? (1.0f / 64.0f) : 1.0f;
        float* out = (z == 0) ? Qt : Kt;
        #pragma unroll
        for (int p = 0; p < 4; p++) {
            float2 f0 = unpack2(acc[p][0]);   // col c0  : rows (s, s+1)
            float2 f1 = unpack2(acc[p][1]);   // col c0+1: rows (s, s+1)
            int s = s0 + w8 + 2 * p;
            size_t base0 = ((size_t)(b * EE + o0 + c0)) * SQ + s;
            *(float2*)&out[base0]      = make_float2((f0.x + bias0) * scale, (f0.y + bias0) * scale);
            *(float2*)&out[base0 + SQ] = make_float2((f1.x + bias1) * scale, (f1.y + bias1) * scale);
        }
    }
}

// ---------------- Flash attention, fp32, online softmax ----------------
// Q/K transposed globals -> straight cp.async staging, no smem transposes.
// grid = (S/BQ, B), block = 256 (8 warps). Warp w owns q-rows w*8..w*8+7 in both phases.
__global__ __launch_bounds__(256, 1) void flash_kernel(
    const float* __restrict__ Qt_g, const float* __restrict__ Kt_g, const float* __restrict__ Vg,
    float* __restrict__ O)
{
    extern __shared__ __align__(16) float sm[];
    float* Qs = sm;                 // [E][64]
    float* Ks = Qs + EE * 64;       // [E][64]
    float* Vs = Ks + EE * 64;       // [64][E]
    float* Ps = Vs + BK * EE;       // [64][64]

    const int b  = blockIdx.y;
    const int q0 = blockIdx.x * BQ;
    const float* Qg = Qt_g + (size_t)b * EE * SQ;
    const float* Kg = Kt_g + (size_t)b * EE * SQ;
    const float* Vb = Vg   + (size_t)b * SQ * EE;

    const int tid = threadIdx.x, lane = tid & 31, warp = tid >> 5;
    const int c0 = lane * 2, w8 = warp * 8, e8 = lane * 8;
    const int rr = tid >> 4, cc = (tid & 15) * 4;

    // stage Q once (rows e = rr+16j, cols q0+cc..)
    {
        uint32_t qd = smem_u32(Qs + rr * 64 + cc);
        const float* qs = Qg + (size_t)rr * SQ + q0 + cc;
        #pragma unroll
        for (int j = 0; j < 16; j++)
            cp16(qd + j * (16 * 64 * 4), qs + (size_t)j * 16 * SQ);
        CP_COMMIT();
    }
    uint32_t kd0 = smem_u32(Ks + rr * 64 + cc);
    const float* kbase = Kg + (size_t)rr * SQ + cc;
    uint32_t vd0 = smem_u32(Vs) + tid * 16;
    const float* vbase = Vb + tid * 4;

    auto stageK = [&](int t) {
        const float* ks = kbase + t * 64;
        #pragma unroll
        for (int j = 0; j < 16; j++)
            cp16(kd0 + j * (16 * 64 * 4), ks + (size_t)j * 16 * SQ);
        CP_COMMIT();
    };
    auto stageV = [&](int t) {
        const float* vs = vbase + (size_t)t * BK * EE;
        #pragma unroll
        for (int i = 0; i < 16; i++)
            cp16(vd0 + i * (256 * 16), vs + i * 1024);
        CP_COMMIT();
    };
    stageK(0);
    stageV(0);

    float m_r[8], l_r[8];
    #pragma unroll
    for (int r = 0; r < 8; r++) { m_r[r] = -1e30f; l_r[r] = 0.0f; }
    ull o2[8][4] = {};   // O accumulators: 8 q-rows x 4 e-pairs

    const int NT = SQ / BK;
    for (int t = 0; t < NT; t++) {
        CP_WAIT0();          // K(t), V(t) (and Q at t=0) landed
        __syncthreads();

        // --- S = Q K^T: thread -> rows w8..w8+7 (pairs), cols c0, c0+1 ---
        ull acc[4][2] = {};
        #pragma unroll 4
        for (int k = 0; k < EE; k++) {
            const float* qr = Qs + k * 64 + w8;          // warp-broadcast
            ulonglong2 a01 = *(const ulonglong2*)qr;
            ulonglong2 a23 = *(const ulonglong2*)(qr + 4);
            float2 kv2 = *(const float2*)(Ks + k * 64 + c0);
            ull b0 = dup2(kv2.x), b1 = dup2(kv2.y);
            ffma2(acc[0][0], a01.x, b0); ffma2(acc[0][1], a01.x, b1);
            ffma2(acc[1][0], a01.y, b0); ffma2(acc[1][1], a01.y, b1);
            ffma2(acc[2][0], a23.x, b0); ffma2(acc[2][1], a23.x, b1);
            ffma2(acc[3][0], a23.y, b0); ffma2(acc[3][1], a23.y, b1);
        }
        float sv[8][2];
        #pragma unroll
        for (int p = 0; p < 4; p++) {
            float2 f0 = unpack2(acc[p][0]);
            float2 f1 = unpack2(acc[p][1]);
            sv[2*p][0]   = f0.x;  sv[2*p][1]   = f1.x;
            sv[2*p+1][0] = f0.y;  sv[2*p+1][1] = f1.y;
        }

        // --- online softmax per row (row spread over 32 lanes x 2 cols) ---
        float alpha[8];
        #pragma unroll
        for (int r = 0; r < 8; r++) {
            float mx = fmaxf(sv[r][0], sv[r][1]);
            #pragma unroll
            for (int sh = 16; sh; sh >>= 1)
                mx = fmaxf(mx, __shfl_xor_sync(0xffffffffu, mx, sh));
            float mnew = fmaxf(m_r[r], mx);
            float a  = __expf(m_r[r] - mnew);
            float p0 = __expf(sv[r][0] - mnew);
            float p1 = __expf(sv[r][1] - mnew);
            float s = p0 + p1;
            #pragma unroll
            for (int sh = 16; sh; sh >>= 1)
                s += __shfl_xor_sync(0xffffffffu, s, sh);
            l_r[r] = l_r[r] * a + s;
            m_r[r] = mnew;
            alpha[r] = a;
            *(float2*)&Ps[(w8 + r) * BK + c0] = make_float2(p0, p1);
        }

        __syncthreads();                    // all Ks reads done
        if (t + 1 < NT) stageK(t + 1);      // hidden behind PV

        // --- O = O*alpha + P V ; thread -> rows w8..w8+7, e cols e8..e8+7 ---
        #pragma unroll
        for (int r = 0; r < 8; r++) {
            ull ad = dup2(alpha[r]);
            fmul2(o2[r][0], ad); fmul2(o2[r][1], ad);
            fmul2(o2[r][2], ad); fmul2(o2[r][3], ad);
        }
        #pragma unroll 2
        for (int kv = 0; kv < BK; kv++) {
            const float* vr = &Vs[kv * EE + e8];
            ulonglong2 v01 = *(const ulonglong2*)vr;
            ulonglong2 v23 = *(const ulonglong2*)(vr + 4);
            #pragma unroll
            for (int r = 0; r < 8; r++) {
                ull pd = dup2(Ps[(w8 + r) * BK + kv]);   // warp-broadcast
                ffma2(o2[r][0], pd, v01.x); ffma2(o2[r][1], pd, v01.y);
                ffma2(o2[r][2], pd, v23.x); ffma2(o2[r][3], pd, v23.y);
            }
        }

        __syncthreads();                    // all Vs reads done
        if (t + 1 < NT) stageV(t + 1);
    }

    // epilogue: normalize by l, store row-major
    const size_t base = (size_t)b * SQ * EE;
    #pragma unroll
    for (int r = 0; r < 8; r++) {
        ull iv = dup2(1.0f / l_r[r]);
        fmul2(o2[r][0], iv); fmul2(o2[r][1], iv);
        fmul2(o2[r][2], iv); fmul2(o2[r][3], iv);
        float* orow = O + base + (size_t)(q0 + w8 + r) * EE + e8;
        float2 f0 = unpack2(o2[r][0]), f1 = unpack2(o2[r][1]);
        float2 f2 = unpack2(o2[r][2]), f3 = unpack2(o2[r][3]);
        *(float4*)orow       = make_float4(f0.x, f0.y, f1.x, f1.y);
        *(float4*)(orow + 4) = make_float4(f2.x, f2.y, f3.x, f3.y);
    }
}

// ---------------- residual add + LayerNorm; optional transposed copy for next qkv ----------------
__global__ __launch_bounds__(256, 1) void add_ln_kernel(
    const float* __restrict__ A, const float* __restrict__ R,
    const float* __restrict__ g, const float* __restrict__ beta,
    float* __restrict__ out, float* __restrict__ out_t)
{
    __shared__ float red0[8];
    __shared__ float red1[8];
    const int row = blockIdx.x;
    const int e   = threadIdx.x;
    const size_t idx = (size_t)row * EE + e;
    float v  = A[idx] + R[idx];
    float s  = v;
    float s2 = v * v;
    #pragma unroll
    for (int sh = 16; sh; sh >>= 1) {
        s  += __shfl_xor_sync(0xffffffffu, s,  sh);
        s2 += __shfl_xor_sync(0xffffffffu, s2, sh);
    }
    const int lane = e & 31, warp = e >> 5;
    if (lane == 0) { red0[warp] = s; red1[warp] = s2; }
    __syncthreads();
    if (warp == 0) {
        float a  = red0[lane & 7];
        float b2 = red1[lane & 7];
        #pragma unroll
        for (int sh = 4; sh; sh >>= 1) {
            a  += __shfl_xor_sync(0xffffffffu, a,  sh);
            b2 += __shfl_xor_sync(0xffffffffu, b2, sh);
        }
        if (lane == 0) { red0[0] = a; red1[0] = b2; }
    }
    __syncthreads();
    const float mu  = red0[0] * (1.0f / EE);
    const float var = red1[0] * (1.0f / EE) - mu * mu;
    const float rs  = rsqrtf(var + 1e-5f);
    const float y   = (v - mu) * rs * g[e] + beta[e];
    out[idx] = y;
    if (out_t) {
        const int bidx = row >> 12;          // SQ = 4096
        const int sidx = row & (SQ - 1);
        out_t[((size_t)(bidx * EE + e)) * SQ + sidx] = y;
    }
}

// ---------------- host launch ----------------
extern "C" void kernel_launch(void* const* d_in, const int* in_sizes, int n_in,
                              void* d_out, int out_size)
{
    (void)in_sizes; (void)n_in; (void)out_size;
    const float* x   = (const float*)d_in[0];
    const float* W1[3] = { (const float*)d_in[1], (const float*)d_in[3], (const float*)d_in[5] };
    const float* b1[3] = { (const float*)d_in[2], (const float*)d_in[4], (const float*)d_in[6] };
    const float* W2[3] = { (const float*)d_in[7], (const float*)d_in[9], (const float*)d_in[11] };
    const float* b2[3] = { (const float*)d_in[8], (const float*)d_in[10], (const float*)d_in[12] };
    const float* g1  = (const float*)d_in[13];
    const float* be1 = (const float*)d_in[14];
    const float* g2  = (const float*)d_in[15];
    const float* be2 = (const float*)d_in[16];
    float* out = (float*)d_out;

    float *qt, *kt, *v, *attn, *o1, *xt, *wt;
    cudaGetSymbolAddress((void**)&qt,   g_qt);
    cudaGetSymbolAddress((void**)&kt,   g_kt);
    cudaGetSymbolAddress((void**)&v,    g_v);
    cudaGetSymbolAddress((void**)&attn, g_attn);
    cudaGetSymbolAddress((void**)&o1,   g_o1);
    cudaGetSymbolAddress((void**)&xt,   g_xt);
    cudaGetSymbolAddress((void**)&wt,   g_wt);

    const int smem_qkv   = 2 * 4096 * 2 * (int)sizeof(float);                       // 64 KB
    const int smem_flash = (EE * 64 * 2 + BK * EE + BQ * BK) * (int)sizeof(float);  // 208 KB
    cudaFuncSetAttribute(qkv_kernel,   cudaFuncAttributeMaxDynamicSharedMemorySize, smem_qkv);
    cudaFuncSetAttribute(flash_kernel, cudaFuncAttributeMaxDynamicSharedMemorySize, smem_flash);

    dim3 tb(32, 8);
    // x -> xt (per-batch transpose [SQ,EE] -> [EE,SQ])
    transpose_kernel<<<dim3(EE / 32, SQ / 32, BB), tb>>>(x, xt, SQ, EE);
    // 6 weight transposes [o][e] -> [e][o]
    for (int i = 0; i < 3; i++) {
        transpose_kernel<<<dim3(EE / 32, EE / 32, 1), tb>>>(W1[i], wt + (size_t)i * EE * EE, EE, EE);
        transpose_kernel<<<dim3(EE / 32, EE / 32, 1), tb>>>(W2[i], wt + (size_t)(3 + i) * EE * EE, EE, EE);
    }

    dim3 gq(M_TOT / 64, EE / 64, 3);
    dim3 gf(SQ / BQ, BB);

    // layer 1
    qkv_kernel<<<gq, 256, smem_qkv>>>(xt, wt, b1[0], b1[1], b1[2], qt, kt, v);
    flash_kernel<<<gf, 256, smem_flash>>>(qt, kt, v, attn);
    add_ln_kernel<<<M_TOT, 256>>>(attn, x, g1, be1, o1, xt);   // also emits xt for layer 2
    // layer 2
    qkv_kernel<<<gq, 256, smem_qkv>>>(xt, wt + (size_t)3 * EE * EE, b2[0], b2[1], b2[2], qt, kt, v);
    flash_kernel<<<gf, 256, smem_flash>>>(qt, kt, v, attn);
    add_ln_kernel<<<M_TOT, 256>>>(attn, o1, g2, be2, out, nullptr);
}

// round 16
// speedup vs baseline: 1.4319x; 1.0002x over previous
#include <cuda_runtime.h>
#include <stdint.h>

// Problem constants
#define BB 4
#define SQ 4096
#define EE 256
#define M_TOT (BB*SQ)        // 16384 rows
#define BQ 64
#define BK 64

// ---------------- scratch (static device globals; no allocation) ----------------
__device__ __align__(16) float g_qt[BB*SQ*EE];     // Q transposed [B][E][S], pre-scaled
__device__ __align__(16) float g_kt[BB*SQ*EE];     // K transposed [B][E][S]
__device__ __align__(16) float g_v [BB*SQ*EE];     // V row-major  [B][S][E]
__device__ __align__(16) float g_attn[BB*SQ*EE];   // attention out, row-major
__device__ __align__(16) float g_o1[BB*SQ*EE];     // layer-1 output, row-major
__device__ __align__(16) float g_xt[BB*SQ*EE];     // qkv input, transposed [B][E][S]
__device__ __align__(16) float g_wt[6*EE*EE];      // 6 transposed weights [E_in][E_out]

typedef unsigned long long ull;

// ---------------- packed f32x2 helpers (FFMA2: 2x fp32 FMA throughput) ----------------
__device__ __forceinline__ ull pack2(float lo, float hi) {
    ull r; asm("mov.b64 %0, {%1,%2};" : "=l"(r) : "f"(lo), "f"(hi)); return r;
}
__device__ __forceinline__ ull dup2(float x) { return pack2(x, x); }
__device__ __forceinline__ float2 unpack2(ull v) {
    float2 f; asm("mov.b64 {%0,%1}, %2;" : "=f"(f.x), "=f"(f.y) : "l"(v)); return f;
}
__device__ __forceinline__ void ffma2(ull& d, ull a, ull b) {
    asm("fma.rn.f32x2 %0, %1, %2, %0;" : "+l"(d) : "l"(a), "l"(b));
}
__device__ __forceinline__ void fmul2(ull& d, ull a) {
    asm("mul.rn.f32x2 %0, %0, %1;" : "+l"(d) : "l"(a));
}

// ---------------- cp.async helpers ----------------
__device__ __forceinline__ uint32_t smem_u32(const void* p) {
    return (uint32_t)__cvta_generic_to_shared(p);
}
__device__ __forceinline__ void cp16(uint32_t dst, const void* src) {
    asm volatile("cp.async.cg.shared.global [%0], [%1], 16;\n" :: "r"(dst), "l"(src));
}
#define CP_COMMIT() asm volatile("cp.async.commit_group;\n" ::: "memory")
#define CP_WAIT0()  asm volatile("cp.async.wait_group 0;\n" ::: "memory")
#define CP_WAIT1()  asm volatile("cp.async.wait_group 1;\n" ::: "memory")

// ---------------- generic slab transpose: in [z][R][C] -> out [z][C][R] ----------------
__global__ void transpose_kernel(const float* __restrict__ in, float* __restrict__ out,
                                 int R, int C)
{
    __shared__ float t[32][33];
    const float* inp = in  + (size_t)blockIdx.z * R * C;
    float*       outp = out + (size_t)blockIdx.z * R * C;
    const int c0 = blockIdx.x * 32, r0 = blockIdx.y * 32;
    const int x = threadIdx.x, y = threadIdx.y;        // block (32, 8)
    #pragma unroll
    for (int j = 0; j < 32; j += 8)
        t[y + j][x] = inp[(size_t)(r0 + y + j) * C + c0 + x];
    __syncthreads();
    #pragma unroll
    for (int j = 0; j < 32; j += 8)
        outp[(size_t)(c0 + y + j) * R + r0 + x] = t[x][y + j];
}

// ---------------- QKV projection ----------------
// Inputs pre-transposed: Xt [B][E][S], Wt [E_in][E_out] per slab.
// Outputs: Q transposed+scaled, K transposed, V row-major.
// grid = (M_TOT/64, EE/64, 3), block = 256. All staging via cp.async (double-buffered).
__global__ __launch_bounds__(256, 1) void qkv_kernel(
    const float* __restrict__ Xt, const float* __restrict__ Wt,
    const float* __restrict__ bq, const float* __restrict__ bk, const float* __restrict__ bv,
    float* __restrict__ Qt, float* __restrict__ Kt, float* __restrict__ V)
{
    extern __shared__ __align__(16) float sm[];
    float* Xs = sm;             // [2][64][64]
    float* Ws = sm + 2 * 4096;  // [2][64][64]

    const int z = blockIdx.z;
    const float* W    = Wt + (size_t)z * EE * EE;
    const float* bias = (z == 0) ? bq : (z == 1) ? bk : bv;

    const int m0 = blockIdx.x * 64;
    const int b  = m0 / SQ, s0 = m0 % SQ;
    const int o0 = blockIdx.y * 64;
    const int tid = threadIdx.x, lane = tid & 31, warp = tid >> 5;
    const int c0 = lane * 2, w8 = warp * 8;
    const int rr = tid >> 4, cc = (tid & 15) * 4;   // staging: row rr(+16j), 16B chunk cc

    const float* xbase = Xt + ((size_t)(b * EE + rr) * SQ + s0) + cc;
    const float* wbase = W  + (size_t)rr * EE + o0 + cc;

    // stage k-tile kt into buffer buf
    auto stage = [&](int kt, int buf) {
        uint32_t xd = smem_u32(Xs + buf * 4096 + rr * 64 + cc);
        uint32_t wd = smem_u32(Ws + buf * 4096 + rr * 64 + cc);
        const float* xs = xbase + (size_t)(kt * 64) * SQ;
        const float* ws = wbase + (size_t)(kt * 64) * EE;
        #pragma unroll
        for (int j = 0; j < 4; j++) {
            cp16(xd + j * (16 * 64 * 4), xs + (size_t)j * 16 * SQ);
            cp16(wd + j * (16 * 64 * 4), ws + (size_t)j * 16 * EE);
        }
        CP_COMMIT();
    };

    stage(0, 0);
    ull acc[4][2] = {};

    for (int kt = 0; kt < 4; kt++) {
        __syncthreads();                  // previous compute's smem reads done
        if (kt < 3) { stage(kt + 1, (kt + 1) & 1); CP_WAIT1(); }
        else        { CP_WAIT0(); }
        __syncthreads();

        const float* Xb = Xs + (kt & 1) * 4096;
        const float* Wb = Ws + (kt & 1) * 4096;
        #pragma unroll 8
        for (int k = 0; k < 64; k++) {
            const float* xr = Xb + k * 64 + w8;          // broadcast within warp
            ulonglong2 a01 = *(const ulonglong2*)xr;
            ulonglong2 a23 = *(const ulonglong2*)(xr + 4);
            float2 bv2 = *(const float2*)(Wb + k * 64 + c0);
            ull b0 = dup2(bv2.x), b1 = dup2(bv2.y);
            ffma2(acc[0][0], a01.x, b0); ffma2(acc[0][1], a01.x, b1);
            ffma2(acc[1][0], a01.y, b0); ffma2(acc[1][1], a01.y, b1);
            ffma2(acc[2][0], a23.x, b0); ffma2(acc[2][1], a23.x, b1);
            ffma2(acc[3][0], a23.y, b0); ffma2(acc[3][1], a23.y, b1);
        }
    }

    const float bias0 = bias[o0 + c0];
    const float bias1 = bias[o0 + c0 + 1];

    if (z == 2) {
        // V: row-major [m][o]
        #pragma unroll
        for (int p = 0; p < 4; p++) {
            float2 f0 = unpack2(acc[p][0]);
            float2 f1 = unpack2(acc[p][1]);
            size_t r0i = (size_t)(m0 + w8 + 2 * p) * EE + o0 + c0;
            *(float2*)&V[r0i]      = make_float2(f0.x + bias0, f1.x + bias1);
            *(float2*)&V[r0i + EE] = make_float2(f0.y + bias0, f1.y + bias1);
        }
    } else {
        // Q/K: transposed [B][E][S]; Q pre-scaled by 1/sqrt(S)=1/64
        const float scale = (z == 0) ? (1.0f / 64.0f) : 1.0f;
        float* out = (z == 0) ? Qt : Kt;
        #pragma unroll
        for (int p = 0; p < 4; p++) {
            float2 f0 = unpack2(acc[p][0]);   // col c0  : rows (s, s+1)
            float2 f1 = unpack2(acc[p][1]);   // col c0+1: rows (s, s+1)
            int s = s0 + w8 + 2 * p;
            size_t base0 = ((size_t)(b * EE + o0 + c0)) * SQ + s;
            *(float2*)&out[base0]      = make_float2((f0.x + bias0) * scale, (f0.y + bias0) * scale);
            *(float2*)&out[base0 + SQ] = make_float2((f1.x + bias1) * scale, (f1.y + bias1) * scale);
        }
    }
}

// ---------------- Flash attention, fp32, online softmax ----------------
// Q/K transposed globals -> straight cp.async staging, no smem transposes.
// grid = (S/BQ, B), block = 256 (8 warps). Warp w owns q-rows w*8..w*8+7 in both phases.
__global__ __launch_bounds__(256, 1) void flash_kernel(
    const float* __restrict__ Qt_g, const float* __restrict__ Kt_g, const float* __restrict__ Vg,
    float* __restrict__ O)
{
    extern __shared__ __align__(16) float sm[];
    float* Qs = sm;                 // [E][64]
    float* Ks = Qs + EE * 64;       // [E][64]
    float* Vs = Ks + EE * 64;       // [64][E]
    float* Ps = Vs + BK * EE;       // [64][64]

    const int b  = blockIdx.y;
    const int q0 = blockIdx.x * BQ;
    const float* Qg = Qt_g + (size_t)b * EE * SQ;
    const float* Kg = Kt_g + (size_t)b * EE * SQ;
    const float* Vb = Vg   + (size_t)b * SQ * EE;

    const int tid = threadIdx.x, lane = tid & 31, warp = tid >> 5;
    const int c0 = lane * 2, w8 = warp * 8, e8 = lane * 8;
    const int rr = tid >> 4, cc = (tid & 15) * 4;

    // stage Q once (rows e = rr+16j, cols q0+cc..)
    {
        uint32_t qd = smem_u32(Qs + rr * 64 + cc);
        const float* qs = Qg + (size_t)rr * SQ + q0 + cc;
        #pragma unroll
        for (int j = 0; j < 16; j++)
            cp16(qd + j * (16 * 64 * 4), qs + (size_t)j * 16 * SQ);
        CP_COMMIT();
    }
    uint32_t kd0 = smem_u32(Ks + rr * 64 + cc);
    const float* kbase = Kg + (size_t)rr * SQ + cc;
    uint32_t vd0 = smem_u32(Vs) + tid * 16;
    const float* vbase = Vb + tid * 4;

    auto stageK = [&](int t) {
        const float* ks = kbase + t * 64;
        #pragma unroll
        for (int j = 0; j < 16; j++)
            cp16(kd0 + j * (16 * 64 * 4), ks + (size_t)j * 16 * SQ);
        CP_COMMIT();
    };
    auto stageV = [&](int t) {
        const float* vs = vbase + (size_t)t * BK * EE;
        #pragma unroll
        for (int i = 0; i < 16; i++)
            cp16(vd0 + i * (256 * 16), vs + i * 1024);
        CP_COMMIT();
    };
    stageK(0);
    stageV(0);

    float m_r[8], l_r[8];
    #pragma unroll
    for (int r = 0; r < 8; r++) { m_r[r] = -1e30f; l_r[r] = 0.0f; }
    ull o2[8][4] = {};   // O accumulators: 8 q-rows x 4 e-pairs

    const int NT = SQ / BK;
    for (int t = 0; t < NT; t++) {
        CP_WAIT0();          // K(t), V(t) (and Q at t=0) landed
        __syncthreads();

        // --- S = Q K^T: thread -> rows w8..w8+7 (pairs), cols c0, c0+1 ---
        ull acc[4][2] = {};
        #pragma unroll 4
        for (int k = 0; k < EE; k++) {
            const float* qr = Qs + k * 64 + w8;          // warp-broadcast
            ulonglong2 a01 = *(const ulonglong2*)qr;
            ulonglong2 a23 = *(const ulonglong2*)(qr + 4);
            float2 kv2 = *(const float2*)(Ks + k * 64 + c0);
            ull b0 = dup2(kv2.x), b1 = dup2(kv2.y);
            ffma2(acc[0][0], a01.x, b0); ffma2(acc[0][1], a01.x, b1);
            ffma2(acc[1][0], a01.y, b0); ffma2(acc[1][1], a01.y, b1);
            ffma2(acc[2][0], a23.x, b0); ffma2(acc[2][1], a23.x, b1);
            ffma2(acc[3][0], a23.y, b0); ffma2(acc[3][1], a23.y, b1);
        }
        float sv[8][2];
        #pragma unroll
        for (int p = 0; p < 4; p++) {
            float2 f0 = unpack2(acc[p][0]);
            float2 f1 = unpack2(acc[p][1]);
            sv[2*p][0]   = f0.x;  sv[2*p][1]   = f1.x;
            sv[2*p+1][0] = f0.y;  sv[2*p+1][1] = f1.y;
        }

        // --- online softmax per row (row spread over 32 lanes x 2 cols) ---
        float alpha[8];
        #pragma unroll
        for (int r = 0; r < 8; r++) {
            float mx = fmaxf(sv[r][0], sv[r][1]);
            #pragma unroll
            for (int sh = 16; sh; sh >>= 1)
                mx = fmaxf(mx, __shfl_xor_sync(0xffffffffu, mx, sh));
            float mnew = fmaxf(m_r[r], mx);
            float a  = __expf(m_r[r] - mnew);
            float p0 = __expf(sv[r][0] - mnew);
            float p1 = __expf(sv[r][1] - mnew);
            float s = p0 + p1;
            #pragma unroll
            for (int sh = 16; sh; sh >>= 1)
                s += __shfl_xor_sync(0xffffffffu, s, sh);
            l_r[r] = l_r[r] * a + s;
            m_r[r] = mnew;
            alpha[r] = a;
            *(float2*)&Ps[(w8 + r) * BK + c0] = make_float2(p0, p1);
        }

        __syncthreads();                    // all Ks reads done
        if (t + 1 < NT) stageK(t + 1);      // hidden behind PV

        // --- O = O*alpha + P V ; thread -> rows w8..w8+7, e cols e8..e8+7 ---
        #pragma unroll
        for (int r = 0; r < 8; r++) {
            ull ad = dup2(alpha[r]);
            fmul2(o2[r][0], ad); fmul2(o2[r][1], ad);
            fmul2(o2[r][2], ad); fmul2(o2[r][3], ad);
        }
        #pragma unroll 2
        for (int kv = 0; kv < BK; kv++) {
            const float* vr = &Vs[kv * EE + e8];
            ulonglong2 v01 = *(const ulonglong2*)vr;
            ulonglong2 v23 = *(const ulonglong2*)(vr + 4);
            #pragma unroll
            for (int r = 0; r < 8; r++) {
                ull pd = dup2(Ps[(w8 + r) * BK + kv]);   // warp-broadcast
                ffma2(o2[r][0], pd, v01.x); ffma2(o2[r][1], pd, v01.y);
                ffma2(o2[r][2], pd, v23.x); ffma2(o2[r][3], pd, v23.y);
            }
        }

        __syncthreads();                    // all Vs reads done
        if (t + 1 < NT) stageV(t + 1);
    }

    // epilogue: normalize by l, store row-major
    const size_t base = (size_t)b * SQ * EE;
    #pragma unroll
    for (int r = 0; r < 8; r++) {
        ull iv = dup2(1.0f / l_r[r]);
        fmul2(o2[r][0], iv); fmul2(o2[r][1], iv);
        fmul2(o2[r][2], iv); fmul2(o2[r][3], iv);
        float* orow = O + base + (size_t)(q0 + w8 + r) * EE + e8;
        float2 f0 = unpack2(o2[r][0]), f1 = unpack2(o2[r][1]);
        float2 f2 = unpack2(o2[r][2]), f3 = unpack2(o2[r][3]);
        *(float4*)orow       = make_float4(f0.x, f0.y, f1.x, f1.y);
        *(float4*)(orow + 4) = make_float4(f2.x, f2.y, f3.x, f3.y);
    }
}

// ---------------- residual add + LayerNorm; optional transposed copy for next qkv ----------------
__global__ __launch_bounds__(256, 1) void add_ln_kernel(
    const float* __restrict__ A, const float* __restrict__ R,
    const float* __restrict__ g, const float* __restrict__ beta,
    float* __restrict__ out, float* __restrict__ out_t)
{
    __shared__ float red0[8];
    __shared__ float red1[8];
    const int row = blockIdx.x;
    const int e   = threadIdx.x;
    const size_t idx = (size_t)row * EE + e;
    float v  = A[idx] + R[idx];
    float s  = v;
    float s2 = v * v;
    #pragma unroll
    for (int sh = 16; sh; sh >>= 1) {
        s  += __shfl_xor_sync(0xffffffffu, s,  sh);
        s2 += __shfl_xor_sync(0xffffffffu, s2, sh);
    }
    const int lane = e & 31, warp = e >> 5;
    if (lane == 0) { red0[warp] = s; red1[warp] = s2; }
    __syncthreads();
    if (warp == 0) {
        float a  = red0[lane & 7];
        float b2 = red1[lane & 7];
        #pragma unroll
        for (int sh = 4; sh; sh >>= 1) {
            a  += __shfl_xor_sync(0xffffffffu, a,  sh);
            b2 += __shfl_xor_sync(0xffffffffu, b2, sh);
        }
        if (lane == 0) { red0[0] = a; red1[0] = b2; }
    }
    __syncthreads();
    const float mu  = red0[0] * (1.0f / EE);
    const float var = red1[0] * (1.0f / EE) - mu * mu;
    const float rs  = rsqrtf(var + 1e-5f);
    const float y   = (v - mu) * rs * g[e] + beta[e];
    out[idx] = y;
    if (out_t) {
        const int bidx = row >> 12;          // SQ = 4096
        const int sidx = row & (SQ - 1);
        out_t[((size_t)(bidx * EE + e)) * SQ + sidx] = y;
    }
}

// ---------------- host launch ----------------
extern "C" void kernel_launch(void* const* d_in, const int* in_sizes, int n_in,
                              void* d_out, int out_size)
{
    (void)in_sizes; (void)n_in; (void)out_size;
    const float* x   = (const float*)d_in[0];
    const float* W1[3] = { (const float*)d_in[1], (const float*)d_in[3], (const float*)d_in[5] };
    const float* b1[3] = { (const float*)d_in[2], (const float*)d_in[4], (const float*)d_in[6] };
    const float* W2[3] = { (const float*)d_in[7], (const float*)d_in[9], (const float*)d_in[11] };
    const float* b2[3] = { (const float*)d_in[8], (const float*)d_in[10], (const float*)d_in[12] };
    const float* g1  = (const float*)d_in[13];
    const float* be1 = (const float*)d_in[14];
    const float* g2  = (const float*)d_in[15];
    const float* be2 = (const float*)d_in[16];
    float* out = (float*)d_out;

    float *qt, *kt, *v, *attn, *o1, *xt, *wt;
    cudaGetSymbolAddress((void**)&qt,   g_qt);
    cudaGetSymbolAddress((void**)&kt,   g_kt);
    cudaGetSymbolAddress((void**)&v,    g_v);
    cudaGetSymbolAddress((void**)&attn, g_attn);
    cudaGetSymbolAddress((void**)&o1,   g_o1);
    cudaGetSymbolAddress((void**)&xt,   g_xt);
    cudaGetSymbolAddress((void**)&wt,   g_wt);

    const int smem_qkv   = 2 * 4096 * 2 * (int)sizeof(float);                       // 64 KB
    const int smem_flash = (EE * 64 * 2 + BK * EE + BQ * BK) * (int)sizeof(float);  // 208 KB
    cudaFuncSetAttribute(qkv_kernel,   cudaFuncAttributeMaxDynamicSharedMemorySize, smem_qkv);
    cudaFuncSetAttribute(flash_kernel, cudaFuncAttributeMaxDynamicSharedMemorySize, smem_flash);

    dim3 tb(32, 8);
    // x -> xt (per-batch transpose [SQ,EE] -> [EE,SQ])
    transpose_kernel<<<dim3(EE / 32, SQ / 32, BB), tb>>>(x, xt, SQ, EE);
    // 6 weight transposes [o][e] -> [e][o]
    for (int i = 0; i < 3; i++) {
        transpose_kernel<<<dim3(EE / 32, EE / 32, 1), tb>>>(W1[i], wt + (size_t)i * EE * EE, EE, EE);
        transpose_kernel<<<dim3(EE / 32, EE / 32, 1), tb>>>(W2[i], wt + (size_t)(3 + i) * EE * EE, EE, EE);
    }

    dim3 gq(M_TOT / 64, EE / 64, 3);
    dim3 gf(SQ / BQ, BB);

    // layer 1
    qkv_kernel<<<gq, 256, smem_qkv>>>(xt, wt, b1[0], b1[1], b1[2], qt, kt, v);
    flash_kernel<<<gf, 256, smem_flash>>>(qt, kt, v, attn);
    add_ln_kernel<<<M_TOT, 256>>>(attn, x, g1, be1, o1, xt);   // also emits xt for layer 2
    // layer 2
    qkv_kernel<<<gq, 256, smem_qkv>>>(xt, wt + (size_t)3 * EE * EE, b2[0], b2[1], b2[2], qt, kt, v);
    flash_kernel<<<gf, 256, smem_flash>>>(qt, kt, v, attn);
    add_ln_kernel<<<M_TOT, 256>>>(attn, o1, g2, be2, out, nullptr);
}